// round 7
// baseline (speedup 1.0000x reference)
#include <cuda_runtime.h>

#define VDIM 256
#define VSLICE (256L * 256L * 256L)

// ---------------------------------------------------------------------------
// Zero-init: one coalesced float4 per thread.
// ---------------------------------------------------------------------------
__global__ void zero_kernel(float4* __restrict__ out, int n4) {
    int i = blockIdx.x * blockDim.x + threadIdx.x;
    if (i < n4) out[i] = make_float4(0.f, 0.f, 0.f, 0.f);
}

__device__ __forceinline__ void red_v4(float* addr, float a, float b, float c, float d) {
    asm volatile("red.global.add.v4.f32 [%0], {%1, %2, %3, %4};"
                 :: "l"(addr), "f"(a), "f"(b), "f"(c), "f"(d)
                 : "memory");
}
__device__ __forceinline__ void red_v2(float* addr, float a, float b) {
    asm volatile("red.global.add.v2.f32 [%0], {%1, %2};"
                 :: "l"(addr), "f"(a), "f"(b)
                 : "memory");
}

// ---------------------------------------------------------------------------
// Splat one point, but only if its z-half matches passSel (0: iz<128,
// 1: iz>=128). Per corner-row, cheapest RED encoding for the (ix,ix+1) pair.
// ---------------------------------------------------------------------------
__device__ __forceinline__ void splat_one(float x, float y, float z, float f,
                                          float* __restrict__ out, int passSel) {
    float fx = (x + 1.0f) * 127.5f;
    float fy = (y + 1.0f) * 127.5f;
    float fz = (z + 1.0f) * 127.5f;

    float lx = floorf(fx), ly = floorf(fy), lz = floorf(fz);
    int ix = (int)lx, iy = (int)ly, iz = (int)lz;

    // Pass selection on clamped iz (also covers slow-path points).
    int izc = min(max(iz, 0), 254);
    if ((izc >> 7) != passSel) return;

    float tx = fx - lx, ty = fy - ly, tz = fz - lz;

    if ((unsigned)ix < 255u && (unsigned)iy < 255u && (unsigned)iz < 255u) {
        float ax = 1.0f - tx;
        float w[4];
        w[0] = (1.0f - ty) * (1.0f - tz) * f;   // (iy,   iz)
        w[1] = ty * (1.0f - tz) * f;            // (iy+1, iz)
        w[2] = (1.0f - ty) * tz * f;            // (iy,   iz+1)
        w[3] = ty * tz * f;                     // (iy+1, iz+1)
        const long roff[4] = {0L, VDIM, (long)VDIM * VDIM, (long)VDIM * VDIM + VDIM};

        float* rowbase = out + (((long)iz * VDIM + iy) * VDIM);
        int off = ix & 3;

        if ((ix & 1) == 0) {
            #pragma unroll
            for (int c = 0; c < 4; c++)
                red_v2(rowbase + roff[c] + ix, w[c] * ax, w[c] * tx);
        } else if (off != 3) {
            int ixa = ix & ~3;
            #pragma unroll
            for (int c = 0; c < 4; c++)
                red_v4(rowbase + roff[c] + ixa, 0.0f, w[c] * ax, w[c] * tx, 0.0f);
        } else {
            #pragma unroll
            for (int c = 0; c < 4; c++) {
                atomicAdd(rowbase + roff[c] + ix,     w[c] * ax);
                atomicAdd(rowbase + roff[c] + ix + 1, w[c] * tx);
            }
        }
    } else {
        // Exact reference semantics for boundary / out-of-range points.
        #pragma unroll
        for (int dz = 0; dz < 2; dz++)
        #pragma unroll
        for (int dy = 0; dy < 2; dy++)
        #pragma unroll
        for (int dx = 0; dx < 2; dx++) {
            int jx = ix + dx, jy = iy + dy, jz = iz + dz;
            float wq = (dx ? tx : 1.0f - tx) *
                       (dy ? ty : 1.0f - ty) *
                       (dz ? tz : 1.0f - tz) * f;
            if (jx >= 0 && jx < VDIM && jy >= 0 && jy < VDIM &&
                jz >= 0 && jz < VDIM) {
                atomicAdd(out + (((long)jz * VDIM + jy) * VDIM + jx), wq);
            }
        }
    }
}

// ---------------------------------------------------------------------------
// Per-phase splat pass: 4 points/thread, float4 loads, single output slice,
// only points whose z-half == passSel.
// ---------------------------------------------------------------------------
__global__ void splat_kernel(const float4* __restrict__ pts4,
                             const float4* __restrict__ feat4,
                             float* __restrict__ out,
                             float scale, int total, int passSel) {
    int t = blockIdx.x * blockDim.x + threadIdx.x;
    int p0 = t * 4;
    if (p0 >= total) return;

    if (p0 + 3 < total) {
        float4 a  = pts4[3L * t];
        float4 b  = pts4[3L * t + 1];
        float4 c  = pts4[3L * t + 2];
        float4 ff = feat4[t];
        splat_one(a.x, a.y, a.z, ff.x * scale, out, passSel);
        splat_one(a.w, b.x, b.y, ff.y * scale, out, passSel);
        splat_one(b.z, b.w, c.x, ff.z * scale, out, passSel);
        splat_one(c.y, c.z, c.w, ff.w * scale, out, passSel);
    } else {
        const float* pts  = (const float*)pts4;
        const float* feat = (const float*)feat4;
        for (int p = p0; p < total; p++) {
            splat_one(pts[3L * p], pts[3L * p + 1], pts[3L * p + 2],
                      feat[p] * scale, out, passSel);
        }
    }
}

// ---------------------------------------------------------------------------
// kernel_launch: per phase: zero slice, then two z-partitioned splat passes
// (each pass's 32 MB atomic working set stays fully L2-resident).
// ---------------------------------------------------------------------------
extern "C" void kernel_launch(void* const* d_in, const int* in_sizes, int n_in,
                              void* d_out, int out_size) {
    const float* pts  = (const float*)d_in[0];
    const float* feat = (const float*)d_in[1];
    float* out = (float*)d_out;

    int BP = in_sizes[1];   // 3 * P
    int P  = BP / 3;

    int half4 = (int)(VSLICE / 4);   // float4s per slice

    // Phase A: slice 0 (views 0,1; scale 0.5 folds the 2-view mean).
    zero_kernel<<<(half4 + 255) / 256, 256>>>((float4*)out, half4);
    int totalA = 2 * P;
    int tA = (totalA + 3) / 4;
    int gA = (tA + 255) / 256;
    splat_kernel<<<gA, 256>>>((const float4*)pts, (const float4*)feat,
                              out, 0.5f, totalA, 0);
    splat_kernel<<<gA, 256>>>((const float4*)pts, (const float4*)feat,
                              out, 0.5f, totalA, 1);

    // Phase B: slice 1 (view 2).
    float* out1 = out + VSLICE;
    zero_kernel<<<(half4 + 255) / 256, 256>>>((float4*)out1, half4);
    const float* ptsB  = pts + 3L * (long)(2 * P);
    const float* featB = feat + 2L * (long)P;
    int tB = (P + 3) / 4;
    int gB = (tB + 255) / 256;
    splat_kernel<<<gB, 256>>>((const float4*)ptsB, (const float4*)featB,
                              out1, 1.0f, P, 0);
    splat_kernel<<<gB, 256>>>((const float4*)ptsB, (const float4*)featB,
                              out1, 1.0f, P, 1);
}

// round 10
// speedup vs baseline: 1.1182x; 1.1182x over previous
#include <cuda_runtime.h>

#define VDIM 256
#define VSLICE (256L * 256L * 256L)

// ---------------------------------------------------------------------------
// L2 policy helpers (createpolicy + cache_hint forms; direct .L2::evict_*
// modifiers are rejected by ptxas for <256-bit ld/st on sm_103a).
// ---------------------------------------------------------------------------
__device__ __forceinline__ unsigned long long policy_evict_last() {
    unsigned long long p;
    asm("createpolicy.fractional.L2::evict_last.b64 %0, 1.0;" : "=l"(p));
    return p;
}
__device__ __forceinline__ unsigned long long policy_evict_first() {
    unsigned long long p;
    asm("createpolicy.fractional.L2::evict_first.b64 %0, 1.0;" : "=l"(p));
    return p;
}

__device__ __forceinline__ float4 ldg_stream(const float4* p, unsigned long long pol) {
    float4 v;
    asm("ld.global.nc.L2::cache_hint.v4.f32 {%0,%1,%2,%3}, [%4], %5;"
        : "=f"(v.x), "=f"(v.y), "=f"(v.z), "=f"(v.w) : "l"(p), "l"(pol));
    return v;
}

__device__ __forceinline__ void red_f32(float* a, float x, unsigned long long pol) {
    asm volatile("red.global.add.L2::cache_hint.f32 [%0], %1, %2;"
                 :: "l"(a), "f"(x), "l"(pol) : "memory");
}
__device__ __forceinline__ void red_v2(float* a, float x, float y, unsigned long long pol) {
    asm volatile("red.global.add.L2::cache_hint.v2.f32 [%0], {%1,%2}, %3;"
                 :: "l"(a), "f"(x), "f"(y), "l"(pol) : "memory");
}
__device__ __forceinline__ void red_v4(float* a, float x, float y, float z, float w,
                                       unsigned long long pol) {
    asm volatile("red.global.add.L2::cache_hint.v4.f32 [%0], {%1,%2,%3,%4}, %5;"
                 :: "l"(a), "f"(x), "f"(y), "f"(z), "f"(w), "l"(pol) : "memory");
}

// ---------------------------------------------------------------------------
// Zero-init: one coalesced float4 per thread, installed as evict_last so the
// slice is already protected in L2 when the splat starts hitting it.
// ---------------------------------------------------------------------------
__global__ void zero_kernel(float4* __restrict__ out, int n4) {
    int i = blockIdx.x * blockDim.x + threadIdx.x;
    if (i < n4) {
        unsigned long long pol = policy_evict_last();
        asm volatile("st.global.L2::cache_hint.v4.f32 [%0], {%1,%1,%1,%1}, %2;"
                     :: "l"(out + i), "f"(0.0f), "l"(pol) : "memory");
    }
}

// ---------------------------------------------------------------------------
// Splat one point: per corner-row, cheapest RED encoding for the (ix,ix+1)
// pair given ix alignment. All REDs carry the evict_last policy.
// ---------------------------------------------------------------------------
__device__ __forceinline__ void splat_one(float x, float y, float z, float f,
                                          float* __restrict__ out,
                                          unsigned long long pol) {
    float fx = (x + 1.0f) * 127.5f;
    float fy = (y + 1.0f) * 127.5f;
    float fz = (z + 1.0f) * 127.5f;

    float lx = floorf(fx), ly = floorf(fy), lz = floorf(fz);
    int ix = (int)lx, iy = (int)ly, iz = (int)lz;
    float tx = fx - lx, ty = fy - ly, tz = fz - lz;

    if ((unsigned)ix < 255u && (unsigned)iy < 255u && (unsigned)iz < 255u) {
        float ax = 1.0f - tx;
        float w[4];
        w[0] = (1.0f - ty) * (1.0f - tz) * f;   // (iy,   iz)
        w[1] = ty * (1.0f - tz) * f;            // (iy+1, iz)
        w[2] = (1.0f - ty) * tz * f;            // (iy,   iz+1)
        w[3] = ty * tz * f;                     // (iy+1, iz+1)
        const long roff[4] = {0L, VDIM, (long)VDIM * VDIM, (long)VDIM * VDIM + VDIM};

        float* rowbase = out + (((long)iz * VDIM + iy) * VDIM);
        int off = ix & 3;

        if ((ix & 1) == 0) {
            #pragma unroll
            for (int c = 0; c < 4; c++)
                red_v2(rowbase + roff[c] + ix, w[c] * ax, w[c] * tx, pol);
        } else if (off != 3) {
            int ixa = ix & ~3;
            #pragma unroll
            for (int c = 0; c < 4; c++)
                red_v4(rowbase + roff[c] + ixa, 0.0f, w[c] * ax, w[c] * tx, 0.0f, pol);
        } else {
            #pragma unroll
            for (int c = 0; c < 4; c++) {
                red_f32(rowbase + roff[c] + ix,     w[c] * ax, pol);
                red_f32(rowbase + roff[c] + ix + 1, w[c] * tx, pol);
            }
        }
    } else {
        // Exact reference semantics for boundary / out-of-range points.
        #pragma unroll
        for (int dz = 0; dz < 2; dz++)
        #pragma unroll
        for (int dy = 0; dy < 2; dy++)
        #pragma unroll
        for (int dx = 0; dx < 2; dx++) {
            int jx = ix + dx, jy = iy + dy, jz = iz + dz;
            float wq = (dx ? tx : 1.0f - tx) *
                       (dy ? ty : 1.0f - ty) *
                       (dz ? tz : 1.0f - tz) * f;
            if (jx >= 0 && jx < VDIM && jy >= 0 && jy < VDIM &&
                jz >= 0 && jz < VDIM) {
                atomicAdd(out + (((long)jz * VDIM + jy) * VDIM + jx), wq);
            }
        }
    }
}

// ---------------------------------------------------------------------------
// Per-phase splat: 4 points/thread, evict_first float4 streaming loads,
// single output slice.
// ---------------------------------------------------------------------------
__global__ void splat_kernel(const float4* __restrict__ pts4,
                             const float4* __restrict__ feat4,
                             float* __restrict__ out,
                             float scale, int total) {
    int t = blockIdx.x * blockDim.x + threadIdx.x;
    int p0 = t * 4;
    if (p0 >= total) return;

    unsigned long long polL = policy_evict_last();
    unsigned long long polF = policy_evict_first();

    if (p0 + 3 < total) {
        float4 a  = ldg_stream(pts4 + 3L * t,     polF);
        float4 b  = ldg_stream(pts4 + 3L * t + 1, polF);
        float4 c  = ldg_stream(pts4 + 3L * t + 2, polF);
        float4 ff = ldg_stream(feat4 + t,         polF);
        splat_one(a.x, a.y, a.z, ff.x * scale, out, polL);
        splat_one(a.w, b.x, b.y, ff.y * scale, out, polL);
        splat_one(b.z, b.w, c.x, ff.z * scale, out, polL);
        splat_one(c.y, c.z, c.w, ff.w * scale, out, polL);
    } else {
        const float* pts  = (const float*)pts4;
        const float* feat = (const float*)feat4;
        for (int p = p0; p < total; p++) {
            splat_one(pts[3L * p], pts[3L * p + 1], pts[3L * p + 2],
                      feat[p] * scale, out, polL);
        }
    }
}

// ---------------------------------------------------------------------------
// kernel_launch: zero0 -> splatA(slice0) -> zero1 -> splatB(slice1).
// ---------------------------------------------------------------------------
extern "C" void kernel_launch(void* const* d_in, const int* in_sizes, int n_in,
                              void* d_out, int out_size) {
    const float* pts  = (const float*)d_in[0];
    const float* feat = (const float*)d_in[1];
    float* out = (float*)d_out;

    int BP = in_sizes[1];   // 3 * P
    int P  = BP / 3;

    int half4 = (int)(VSLICE / 4);   // float4s per slice

    // Phase A: slice 0 (views 0,1; scale 0.5 folds the 2-view mean).
    zero_kernel<<<(half4 + 255) / 256, 256>>>((float4*)out, half4);
    int totalA = 2 * P;
    int tA = (totalA + 3) / 4;
    splat_kernel<<<(tA + 255) / 256, 256>>>((const float4*)pts,
                                            (const float4*)feat,
                                            out, 0.5f, totalA);

    // Phase B: slice 1 (view 2).
    float* out1 = out + VSLICE;
    zero_kernel<<<(half4 + 255) / 256, 256>>>((float4*)out1, half4);
    const float* ptsB  = pts + 3L * (long)(2 * P);
    const float* featB = feat + 2L * (long)P;
    int tB = (P + 3) / 4;
    splat_kernel<<<(tB + 255) / 256, 256>>>((const float4*)ptsB,
                                            (const float4*)featB,
                                            out1, 1.0f, P);
}